// round 9
// baseline (speedup 1.0000x reference)
#include <cuda_runtime.h>

#define B 4
#define S 128
#define SS (S*S)
#define BSS (B*S*S)

__device__ __align__(16) float g_qb[BSS], g_qe[BSS], g_qs[BSS];
__device__ __align__(16) float g_qbT[BSS], g_qeT[BSS], g_qsT[BSS];
__device__ unsigned char g_edge[BSS];
__device__ unsigned char g_chart[BSS];
__device__ int g_mode_e, g_mode_c;   // 0=uint8, 1=int32, 2=float32

__device__ __forceinline__ void cp16(unsigned sd, const void* gsrc)
{
    asm volatile("cp.async.cg.shared.global [%0], [%1], 16;" :: "r"(sd), "l"(gsrc));
}
#define CP_COMMIT() asm volatile("cp.async.commit_group;" ::: "memory")
#define CP_WAIT(n)  asm volatile("cp.async.wait_group %0;" :: "n"(n) : "memory")

// ---------------------------------------------------------------------------
__global__ void k_detect(const unsigned int* __restrict__ me,
                         const unsigned int* __restrict__ mc)
{
    __shared__ int f[4];
    const int tid = threadIdx.x;
    if (tid < 4) f[tid] = 1;
    __syncthreads();
    if (tid < 64) {
        unsigned v = me[tid];
        if (v != 0u && v != 1u)          atomicAnd(&f[0], 0);
        if (v != 0u && v != 0x3f800000u) atomicAnd(&f[1], 0);
    } else {
        unsigned v = mc[tid - 64];
        if (v != 0u && v != 1u)          atomicAnd(&f[2], 0);
        if (v != 0u && v != 0x3f800000u) atomicAnd(&f[3], 0);
    }
    __syncthreads();
    if (tid == 0) {
        g_mode_e = f[0] ? 1 : (f[1] ? 2 : 0);
        g_mode_c = f[2] ? 1 : (f[3] ? 2 : 0);
    }
}

__global__ void k_prep(const void* __restrict__ se, const void* __restrict__ sc,
                       const float4* __restrict__ sb, const float4* __restrict__ sae,
                       const float4* __restrict__ scn, float4* __restrict__ out)
{
    const int q = blockIdx.x * blockDim.x + threadIdx.x;
    if (q * 4 >= BSS) return;
    const int me = g_mode_e, mc = g_mode_c;
    uchar4 e, c;
    if (me == 1)      { int4 v = ((const int4*)se)[q];
                        e = make_uchar4(v.x != 0, v.y != 0, v.z != 0, v.w != 0); }
    else if (me == 2) { float4 v = ((const float4*)se)[q];
                        e = make_uchar4(v.x != 0.f, v.y != 0.f, v.z != 0.f, v.w != 0.f); }
    else              { uchar4 v = ((const uchar4*)se)[q];
                        e = make_uchar4(v.x != 0, v.y != 0, v.z != 0, v.w != 0); }
    if (mc == 1)      { int4 v = ((const int4*)sc)[q];
                        c = make_uchar4(v.x != 0, v.y != 0, v.z != 0, v.w != 0); }
    else if (mc == 2) { float4 v = ((const float4*)sc)[q];
                        c = make_uchar4(v.x != 0.f, v.y != 0.f, v.z != 0.f, v.w != 0.f); }
    else              { uchar4 v = ((const uchar4*)sc)[q];
                        c = make_uchar4(v.x != 0, v.y != 0, v.z != 0, v.w != 0); }
    ((uchar4*)g_edge)[q]  = e;
    ((uchar4*)g_chart)[q] = c;
    out[q]             = sb[q];
    out[BSS/4 + q]     = sae[q];
    out[2*(BSS/4) + q] = scn[q];
}

__global__ void k_sigmoid(const float* __restrict__ out)
{
    const int idx = blockIdx.x * blockDim.x + threadIdx.x;
    if (idx >= BSS) return;
    const float vb = 1.f / (1.f + __expf(-out[idx]));
    const float ve = 1.f / (1.f + __expf(-out[BSS + idx]));
    const float vs = 1.f / (1.f + __expf(-out[2*BSS + idx]));
    g_qb[idx] = vb; g_qe[idx] = ve; g_qs[idx] = vs;
    const int b = idx >> 14;
    const int r = (idx >> 7) & 127;
    const int c = idx & 127;
    const int t = (b*S + c)*S + r;
    g_qbT[t] = vb; g_qeT[t] = ve; g_qsT[t] = vs;
}

// ---------------------------------------------------------------------------
// k_main: block = (b, i), 512 blocks x 256 threads (8 warps), 3 blocks/SM.
// Warp-local double-buffered cp.async pipeline over the 8 DRAM tensors;
// q rows (L2-resident scratch) via register-prefetched LDG.
// Dynamic smem staging: 8 warps x 2 bufs x 8 segs x 512B = 64KB.
// ---------------------------------------------------------------------------
#define SEGS 8
#define NW 8
#define SMEM_DYN (NW * 2 * SEGS * 128 * 4)

__global__ void __launch_bounds__(256, 3) k_main(
    const float* __restrict__ t_be, const float* __restrict__ t_eb,
    const float* __restrict__ t_bb, const float* __restrict__ t_ee,
    const float* __restrict__ t_cb, const float* __restrict__ t_ce,
    const float* __restrict__ t_gb, const float* __restrict__ t_ge,
    const float* __restrict__ t_sp,
    float* __restrict__ out)
{
    extern __shared__ float stg[];
    const int b    = blockIdx.x >> 7;
    const int i    = blockIdx.x & 127;
    const int tid  = threadIdx.x;
    const int lane = tid & 31;
    const int warp = tid >> 5;

    __shared__ unsigned char sm_sp[S];
    __shared__ float sm_qbT[S];
    __shared__ float sm_ab[S], sm_ae[S], sm_as[S];
    __shared__ float sm_span[256];
    __shared__ short lj_e[S], lj_s[S], lk[S];
    __shared__ int cE[4], cS[4], cK[4];

    // ---- setup (first 128 threads): masks, q row, compacted lists ----
    if (tid < 128) {
        const unsigned char e  = g_edge[(b*S + i)*S + tid];
        const unsigned char c0 = g_chart[b*SS + tid];
        const unsigned char ch = g_chart[(b*S + ((i + S - 1) & 127))*S + tid];
        sm_qbT[tid] = g_qbT[(b*S + i)*S + tid];
        sm_ab[tid] = 0.f; sm_ae[tid] = 0.f; sm_as[tid] = 0.f;

        const bool pE = (e != 0);
        const bool pS = (ch && c0);
        const bool pK = (c0 != 0);
        sm_sp[tid] = pS ? 1 : 0;
        const unsigned bE = __ballot_sync(0xffffffffu, pE);
        const unsigned bS = __ballot_sync(0xffffffffu, pS);
        const unsigned bK = __ballot_sync(0xffffffffu, pK);
        if (lane == 0) { cE[warp] = __popc(bE); cS[warp] = __popc(bS); cK[warp] = __popc(bK); }
        __syncwarp();
        // prefix offsets need other warps' counts -> do after block sync below
        // store ballots temporarily in shared via lane writes
        // (simpler: recompute offsets after __syncthreads using cE/cS/cK)
        // stash ballot in sm_span region (unused yet)
        if (lane == 0) {
            ((unsigned*)sm_span)[warp*3 + 0] = bE;
            ((unsigned*)sm_span)[warp*3 + 1] = bS;
            ((unsigned*)sm_span)[warp*3 + 2] = bK;
        }
    }
    __syncthreads();
    if (tid < 128) {
        const unsigned bE = ((unsigned*)sm_span)[warp*3 + 0];
        const unsigned bS = ((unsigned*)sm_span)[warp*3 + 1];
        const unsigned bK = ((unsigned*)sm_span)[warp*3 + 2];
        int oE = 0, oS = 0, oK = 0;
        #pragma unroll
        for (int w = 0; w < 4; ++w) if (w < warp) { oE += cE[w]; oS += cS[w]; oK += cK[w]; }
        const unsigned lt = (1u << lane) - 1u;
        const bool pE = (bE >> lane) & 1u;
        const bool pS = (bS >> lane) & 1u;
        const bool pK = (bK >> lane) & 1u;
        if (pE) lj_e[oE + __popc(bE & lt)] = (short)tid;
        if (pS) lj_s[oS + __popc(bS & lt)] = (short)tid;
        if (pK) lk [oK + __popc(bK & lt)] = (short)tid;
    }
    __syncthreads();
    const int NE = cE[0] + cE[1] + cE[2] + cE[3];
    const int NS = cS[0] + cS[1] + cS[2] + cS[3];
    const int NK = cK[0] + cK[1] + cK[2] + cK[3];

    // ---- per-lane (4 k's) weight precompute ----
    const int k0 = lane * 4;
    float w_be[4], w_bb[4], w_eb[4], e4[4], pre_wm[4], qsk[4];
    int nc_lo[4], ns_hi[4];
    #pragma unroll
    for (int u = 0; u < 4; ++u) {
        const int k = k0 + u;
        const int q = (b*S + i)*S + k;
        const float e  = (float)g_edge[q];
        const float c0 = (float)g_chart[b*SS + k];
        const float qb = g_qb[q], qe = g_qe[q], qs = g_qs[q];
        e4[u]     = e;
        pre_wm[u] = (i != k) ? e : 0.f;
        w_be[u]   = pre_wm[u] * qe;
        w_bb[u]   = pre_wm[u] * qb;
        w_eb[u]   = e * qb;
        qsk[u]    = c0 * qs;
        nc_lo[u]  = (k <= i) ? 0 : i;      // m_nc: nc_lo <= j <= k
        ns_hi[u]  = (k >= i) ? 127 : i;    // m_ns: k <= j <= ns_hi
    }

    const int row_base = (b*S + i)*S;
    const unsigned stg_u32 = (unsigned)__cvta_generic_to_shared(stg);
    const unsigned sbase = stg_u32 + (unsigned)(warp * 2 * SEGS * 512)
                                   + (unsigned)(k0 * 4);

    #define STAGE(JJ, BF) do {                                              \
        if ((JJ) < NE) {                                                    \
            const int j_  = lj_e[(JJ)];                                     \
            const int off = (row_base + j_)*S + k0;                         \
            const unsigned sd = sbase + (unsigned)((BF) * (SEGS * 512));    \
            cp16(sd + 0*512,  t_be + off);                                  \
            cp16(sd + 1*512,  t_eb + off);                                  \
            cp16(sd + 2*512,  t_bb + off);                                  \
            cp16(sd + 3*512,  t_ee + off);                                  \
            cp16(sd + 4*512,  t_cb + off);                                  \
            cp16(sd + 5*512,  t_ce + off);                                  \
            cp16(sd + 6*512,  t_gb + off);                                  \
            cp16(sd + 7*512,  t_ge + off);                                  \
        }                                                                   \
        CP_COMMIT();                                                        \
    } while (0)

    // ---- phase 1a: warp-local double-buffered pipeline + q LDG prefetch ----
    float4 qbTn = {0,0,0,0}, qeTn = {0,0,0,0}, qsn = {0,0,0,0}, qsTn = {0,0,0,0};
    if (warp < NE) {
        const int qof = (b*S + lj_e[warp])*S + k0;
        qbTn = *(const float4*)(g_qbT + qof);
        qeTn = *(const float4*)(g_qeT + qof);
        qsn  = *(const float4*)(g_qs  + qof);
        qsTn = *(const float4*)(g_qsT + qof);
    }
    STAGE(warp, 0);
    int buf = 0;
    for (int t = warp; t < NE; t += NW) {
        STAGE(t + NW, buf ^ 1);
        const float4 qbTc = qbTn, qeTc = qeTn, qsc = qsn, qsTc = qsTn;
        if (t + NW < NE) {                      // prefetch q for next row
            const int qof = (b*S + lj_e[t + NW])*S + k0;
            qbTn = *(const float4*)(g_qbT + qof);
            qeTn = *(const float4*)(g_qeT + qof);
            qsn  = *(const float4*)(g_qs  + qof);
            qsTn = *(const float4*)(g_qsT + qof);
        }
        CP_WAIT(1);
        const int j = lj_e[t];
        const float* sb = &stg[(warp * 2 + buf) * (SEGS*128) + k0];
        float a_be[4], a_eb[4], a_bb[4], a_ee[4], a_cb[4], a_ce[4], a_gb[4], a_ge[4];
        *(float4*)a_be = *(const float4*)(sb + 0*128);
        *(float4*)a_eb = *(const float4*)(sb + 1*128);
        *(float4*)a_bb = *(const float4*)(sb + 2*128);
        *(float4*)a_ee = *(const float4*)(sb + 3*128);
        *(float4*)a_cb = *(const float4*)(sb + 4*128);
        *(float4*)a_ce = *(const float4*)(sb + 5*128);
        *(float4*)a_gb = *(const float4*)(sb + 6*128);
        *(float4*)a_ge = *(const float4*)(sb + 7*128);
        const float* qbTj = (const float*)&qbTc;
        const float* qeTj = (const float*)&qeTc;
        const float* qsj  = (const float*)&qsc;
        const float* qsTj = (const float*)&qsTc;

        float ab = 0.f, ae1 = 0.f, ae2 = 0.f;
        #pragma unroll
        for (int u = 0; u < 4; ++u) {
            const int k = k0 + u;
            ab  += w_be[u] * a_be[u];
            ab  += w_bb[u] * a_bb[u];
            ab  += (pre_wm[u] * qbTj[u]) * a_cb[u];
            const float wnc = (j >= nc_lo[u] && j <= k) ? pre_wm[u] : 0.f;
            ab  += (wnc * qsj[u]) * a_gb[u];
            ae1 += w_eb[u] * a_eb[u];
            const float wns = (j >= k && j <= ns_hi[u]) ? e4[u] : 0.f;
            ae1 += (wns * qsTj[u]) * a_ge[u];
            ae2 += w_be[u] * a_ee[u];
            ae2 += (pre_wm[u] * qeTj[u]) * a_ce[u];
        }
        // k = j correction for the m_2o (k != j) terms
        #pragma unroll
        for (int u = 0; u < 4; ++u) {
            if (j == k0 + u) {
                ab  -= w_bb[u] * a_bb[u] + (pre_wm[u] * qbTj[u]) * a_cb[u];
                ae2 -= w_be[u] * a_ee[u] + (pre_wm[u] * qeTj[u]) * a_ce[u];
            }
        }
        float ae = ((i != j) ? 1.f : 0.f) * ae1 + ae2;
        #pragma unroll
        for (int o = 16; o; o >>= 1) {
            ab += __shfl_xor_sync(0xffffffffu, ab, o);
            ae += __shfl_xor_sync(0xffffffffu, ae, o);
        }
        if (lane == 0) { sm_ab[j] = ab; sm_ae[j] = ae; }
        buf ^= 1;
    }

    // ---- phase 1b: split term, 4 rows batch-loaded (MLP=4) ----
    for (int jj = warp; jj < NS; jj += NW * 4) {
        float v[4][4];
        int jr[4];
        #pragma unroll
        for (int r = 0; r < 4; ++r) {
            const int idx = jj + r * NW;
            jr[r] = (idx < NS) ? (int)lj_s[idx] : -1;
            if (jr[r] >= 0)
                *(float4*)v[r] = *(const float4*)(t_sp + (row_base + jr[r])*S + k0);
        }
        #pragma unroll
        for (int r = 0; r < 4; ++r) {
            if (jr[r] < 0) break;                  // warp-uniform
            const int j = jr[r];
            const int mx = (i > j) ? i : j;
            float as_ = 0.f;
            #pragma unroll
            for (int u = 0; u < 4; ++u)
                as_ += ((k0 + u != mx) ? qsk[u] : 0.f) * v[r][u];
            #pragma unroll
            for (int o = 16; o; o >>= 1)
                as_ += __shfl_xor_sync(0xffffffffu, as_, o);
            if (lane == 0) sm_as[j] = as_;
        }
    }

    // ---- phase 2: span_grd_b gather; j = tid&127, two k-halves ----
    {
        const int j  = tid & 127;
        const int kh = tid >> 7;
        float span = 0.f;
        if (sm_sp[j]) {
            const int mx = (i > j) ? i : j;
            #pragma unroll 8
            for (int t = kh; t < NK; t += 2) {
                const int k = lk[t];
                const float w = (!((i <= k) && (j >= k)) && (mx != k)) ? sm_qbT[k] : 0.f;
                span += w * t_gb[((b*S + k)*S + i)*S + j];
            }
        }
        __syncthreads();           // sm_span stash from setup no longer needed
        sm_span[tid] = span;
    }
    __syncthreads();

    if (tid < 128) {
        const int o = row_base + tid;
        out[o]         += sm_ab[tid];
        out[BSS + o]   += sm_ae[tid];
        out[2*BSS + o] += sm_as[tid] + sm_span[tid] + sm_span[tid + 128];
    }
}

// ---------------------------------------------------------------------------
// k_spanE: block = (b, j). 512 blocks x 256 threads.
// ---------------------------------------------------------------------------
__global__ void __launch_bounds__(256) k_spanE(
    const float* __restrict__ t_ge,
    float* __restrict__ out)
{
    const int b   = blockIdx.x >> 7;
    const int j   = blockIdx.x & 127;
    const int tid = threadIdx.x;
    const int lane = tid & 31;
    const int warp = tid >> 5;

    if (!g_chart[b*SS + j]) return;

    __shared__ unsigned char sm_chc[S];
    __shared__ float sm_qeT[S];
    __shared__ float sm_acc[256];
    __shared__ short lk[S];
    __shared__ int cK[8];

    bool pK = false;
    if (tid < 128) {
        const unsigned char c0 = g_chart[b*SS + tid];
        pK = (c0 != 0);
        sm_chc[tid] = g_chart[(b*S + ((tid + S - 1) & 127))*S + j];
        sm_qeT[tid] = g_qeT[(b*S + j)*S + tid];
    }
    const unsigned bK = __ballot_sync(0xffffffffu, pK);
    if (lane == 0) cK[warp] = __popc(bK);
    __syncthreads();
    int oK = 0;
    #pragma unroll
    for (int w = 0; w < 8; ++w) if (w < warp) oK += cK[w];
    if (pK) lk[oK + __popc(bK & ((1u << lane) - 1u))] = (short)tid;
    __syncthreads();
    const int NK = cK[0] + cK[1] + cK[2] + cK[3];

    const int i  = tid & 127;
    const int kh = tid >> 7;
    float acc = 0.f;
    if (sm_chc[i]) {
        const int mx = (i > j) ? i : j;
        #pragma unroll 8
        for (int t = kh; t < NK; t += 2) {
            const int k = lk[t];
            const float w = (!((i <= k) && (j >= k)) && (mx != k)) ? sm_qeT[k] : 0.f;
            acc += w * t_ge[((b*S + k)*S + j)*S + i];
        }
    }
    sm_acc[tid] = acc;
    __syncthreads();
    if (tid < 128)
        out[2*BSS + (b*S + tid)*S + j] += sm_acc[tid] + sm_acc[tid + 128];
}

// ---------------------------------------------------------------------------
extern "C" void kernel_launch(void* const* d_in, const int* in_sizes, int n_in,
                              void* d_out, int out_size)
{
    const float* s_const     = (const float*)d_in[0];
    const float* s_arg_begin = (const float*)d_in[1];
    const float* s_arg_end   = (const float*)d_in[2];
    const float* s_sib_be    = (const float*)d_in[3];
    const float* s_sib_eb    = (const float*)d_in[4];
    const float* s_sib_bb    = (const float*)d_in[5];
    const float* s_sib_ee    = (const float*)d_in[6];
    const float* s_cop_b     = (const float*)d_in[7];
    const float* s_cop_e     = (const float*)d_in[8];
    const float* s_grd_b     = (const float*)d_in[9];
    const float* s_grd_e     = (const float*)d_in[10];
    const float* s_split     = (const float*)d_in[11];
    const void*  edge        = d_in[12];
    const void*  chartm      = d_in[13];
    float* out = (float*)d_out;

    // host-side, idempotent, capture-safe
    cudaFuncSetAttribute(k_main, cudaFuncAttributeMaxDynamicSharedMemorySize,
                         SMEM_DYN);

    k_detect<<<1, 128>>>((const unsigned int*)edge, (const unsigned int*)chartm);
    k_prep<<<BSS/4/128, 128>>>(edge, chartm, (const float4*)s_arg_begin,
                               (const float4*)s_arg_end, (const float4*)s_const,
                               (float4*)out);

    for (int it = 0; it < 3; ++it) {
        k_sigmoid<<<BSS/128, 128>>>(out);
        // k_main at launch index 3 on first iter -> ncu capture slot
        k_main<<<B * S, 256, SMEM_DYN>>>(s_sib_be, s_sib_eb, s_sib_bb, s_sib_ee,
                                         s_cop_b, s_cop_e, s_grd_b, s_grd_e,
                                         s_split, out);
        k_spanE<<<B * S, 256>>>(s_grd_e, out);
    }
}

// round 10
// speedup vs baseline: 1.2234x; 1.2234x over previous
#include <cuda_runtime.h>

#define B 4
#define S 128
#define SS (S*S)
#define BSS (B*S*S)

#define NWARP 4
#define SEGS 8
#define SLOTS 3
#define ROW_BYTES (SEGS*512)                       // 4096 per row
#define SMEM_DYN (NWARP * SLOTS * SEGS * 512)      // 48KB

__device__ __align__(16) float g_qb[BSS], g_qe[BSS], g_qs[BSS];
__device__ __align__(16) float g_qbT[BSS], g_qeT[BSS], g_qsT[BSS];
__device__ unsigned char g_edge[BSS];
__device__ unsigned char g_chart[BSS];
__device__ int g_mode_e, g_mode_c;   // 0=uint8, 1=int32, 2=float32

// ---------------------------------------------------------------------------
// bulk-copy 512B global->shared, completion via mbarrier complete_tx
// ---------------------------------------------------------------------------
__device__ __forceinline__ void bulk512(unsigned sd, const void* gsrc, unsigned mb)
{
    asm volatile(
        "cp.async.bulk.shared::cluster.global.mbarrier::complete_tx::bytes [%0], [%1], 512, [%2];"
        :: "r"(sd), "l"(gsrc), "r"(mb) : "memory");
}

__device__ __forceinline__ void mbar_wait(unsigned mb, unsigned par)
{
    asm volatile(
        "{\n\t"
        ".reg .pred P;\n\t"
        "LAB_%=:\n\t"
        "mbarrier.try_wait.parity.acquire.cta.shared::cta.b64 P, [%0], %1, 0x989680;\n\t"
        "@!P bra LAB_%=;\n\t"
        "}"
        :: "r"(mb), "r"(par) : "memory");
}

// ---------------------------------------------------------------------------
__global__ void k_detect(const unsigned int* __restrict__ me,
                         const unsigned int* __restrict__ mc)
{
    __shared__ int f[4];
    const int tid = threadIdx.x;
    if (tid < 4) f[tid] = 1;
    __syncthreads();
    if (tid < 64) {
        unsigned v = me[tid];
        if (v != 0u && v != 1u)          atomicAnd(&f[0], 0);
        if (v != 0u && v != 0x3f800000u) atomicAnd(&f[1], 0);
    } else {
        unsigned v = mc[tid - 64];
        if (v != 0u && v != 1u)          atomicAnd(&f[2], 0);
        if (v != 0u && v != 0x3f800000u) atomicAnd(&f[3], 0);
    }
    __syncthreads();
    if (tid == 0) {
        g_mode_e = f[0] ? 1 : (f[1] ? 2 : 0);
        g_mode_c = f[2] ? 1 : (f[3] ? 2 : 0);
    }
}

__global__ void k_prep(const void* __restrict__ se, const void* __restrict__ sc,
                       const float4* __restrict__ sb, const float4* __restrict__ sae,
                       const float4* __restrict__ scn, float4* __restrict__ out)
{
    const int q = blockIdx.x * blockDim.x + threadIdx.x;
    if (q * 4 >= BSS) return;
    const int me = g_mode_e, mc = g_mode_c;
    uchar4 e, c;
    if (me == 1)      { int4 v = ((const int4*)se)[q];
                        e = make_uchar4(v.x != 0, v.y != 0, v.z != 0, v.w != 0); }
    else if (me == 2) { float4 v = ((const float4*)se)[q];
                        e = make_uchar4(v.x != 0.f, v.y != 0.f, v.z != 0.f, v.w != 0.f); }
    else              { uchar4 v = ((const uchar4*)se)[q];
                        e = make_uchar4(v.x != 0, v.y != 0, v.z != 0, v.w != 0); }
    if (mc == 1)      { int4 v = ((const int4*)sc)[q];
                        c = make_uchar4(v.x != 0, v.y != 0, v.z != 0, v.w != 0); }
    else if (mc == 2) { float4 v = ((const float4*)sc)[q];
                        c = make_uchar4(v.x != 0.f, v.y != 0.f, v.z != 0.f, v.w != 0.f); }
    else              { uchar4 v = ((const uchar4*)sc)[q];
                        c = make_uchar4(v.x != 0, v.y != 0, v.z != 0, v.w != 0); }
    ((uchar4*)g_edge)[q]  = e;
    ((uchar4*)g_chart)[q] = c;
    out[q]             = sb[q];
    out[BSS/4 + q]     = sae[q];
    out[2*(BSS/4) + q] = scn[q];
}

__global__ void k_sigmoid(const float* __restrict__ out)
{
    const int idx = blockIdx.x * blockDim.x + threadIdx.x;
    if (idx >= BSS) return;
    const float vb = 1.f / (1.f + __expf(-out[idx]));
    const float ve = 1.f / (1.f + __expf(-out[BSS + idx]));
    const float vs = 1.f / (1.f + __expf(-out[2*BSS + idx]));
    g_qb[idx] = vb; g_qe[idx] = ve; g_qs[idx] = vs;
    const int b = idx >> 14;
    const int r = (idx >> 7) & 127;
    const int c = idx & 127;
    const int t = (b*S + c)*S + r;
    g_qbT[t] = vb; g_qeT[t] = ve; g_qsT[t] = vs;
}

// ---------------------------------------------------------------------------
// k_main: block = (b, i), 512 blocks x 128 threads, 4 blocks/SM (one wave).
// Warp-local 3-slot cp.async.bulk (TMA-engine) ring; mbarrier completion.
// ---------------------------------------------------------------------------
__global__ void __launch_bounds__(128, 4) k_main(
    const float* __restrict__ t_be, const float* __restrict__ t_eb,
    const float* __restrict__ t_bb, const float* __restrict__ t_ee,
    const float* __restrict__ t_cb, const float* __restrict__ t_ce,
    const float* __restrict__ t_gb, const float* __restrict__ t_ge,
    const float* __restrict__ t_sp,
    float* __restrict__ out)
{
    extern __shared__ float stg[];
    const int b    = blockIdx.x >> 7;
    const int i    = blockIdx.x & 127;
    const int tid  = threadIdx.x;
    const int lane = tid & 31;
    const int warp = tid >> 5;

    __shared__ __align__(8) unsigned long long mbars[NWARP * SLOTS];
    __shared__ unsigned char sm_sp[S];
    __shared__ float sm_qbT[S];
    __shared__ float sm_ab[S], sm_ae[S], sm_as[S];
    __shared__ short lj_e[S], lj_s[S], lk[S];
    __shared__ int cE[4], cS[4], cK[4];

    // ---- setup: mbarriers, masks, q row, ballot-compacted lists ----
    {
        if (tid < NWARP * SLOTS) {
            unsigned mb = (unsigned)__cvta_generic_to_shared(&mbars[tid]);
            asm volatile("mbarrier.init.shared.b64 [%0], 1;" :: "r"(mb) : "memory");
            asm volatile("fence.proxy.async.shared::cta;" ::: "memory");
        }
        const unsigned char e  = g_edge[(b*S + i)*S + tid];
        const unsigned char c0 = g_chart[b*SS + tid];
        const unsigned char ch = g_chart[(b*S + ((i + S - 1) & 127))*S + tid];
        sm_qbT[tid] = g_qbT[(b*S + i)*S + tid];
        sm_ab[tid] = 0.f; sm_ae[tid] = 0.f; sm_as[tid] = 0.f;

        const bool pE = (e != 0);
        const bool pS = (ch && c0);
        const bool pK = (c0 != 0);
        sm_sp[tid] = pS ? 1 : 0;
        const unsigned bE = __ballot_sync(0xffffffffu, pE);
        const unsigned bS = __ballot_sync(0xffffffffu, pS);
        const unsigned bK = __ballot_sync(0xffffffffu, pK);
        if (lane == 0) { cE[warp] = __popc(bE); cS[warp] = __popc(bS); cK[warp] = __popc(bK); }
        __syncthreads();
        int oE = 0, oS = 0, oK = 0;
        #pragma unroll
        for (int w = 0; w < 4; ++w) if (w < warp) { oE += cE[w]; oS += cS[w]; oK += cK[w]; }
        const unsigned lt = (1u << lane) - 1u;
        if (pE) lj_e[oE + __popc(bE & lt)] = (short)tid;
        if (pS) lj_s[oS + __popc(bS & lt)] = (short)tid;
        if (pK) lk [oK + __popc(bK & lt)] = (short)tid;
    }
    __syncthreads();
    const int NE = cE[0] + cE[1] + cE[2] + cE[3];
    const int NS = cS[0] + cS[1] + cS[2] + cS[3];
    const int NK = cK[0] + cK[1] + cK[2] + cK[3];

    // ---- per-lane (4 k's) weight precompute ----
    const int k0 = lane * 4;
    float w_be[4], w_bb[4], w_eb[4], e4[4], pre_wm[4], qsk[4];
    int nc_lo[4], ns_hi[4];
    #pragma unroll
    for (int u = 0; u < 4; ++u) {
        const int k = k0 + u;
        const int q = (b*S + i)*S + k;
        const float e  = (float)g_edge[q];
        const float c0 = (float)g_chart[b*SS + k];
        const float qb = g_qb[q], qe = g_qe[q], qs = g_qs[q];
        e4[u]     = e;
        pre_wm[u] = (i != k) ? e : 0.f;
        w_be[u]   = pre_wm[u] * qe;
        w_bb[u]   = pre_wm[u] * qb;
        w_eb[u]   = e * qb;
        qsk[u]    = c0 * qs;
        nc_lo[u]  = (k <= i) ? 0 : i;      // m_nc: nc_lo <= j <= k
        ns_hi[u]  = (k >= i) ? 127 : i;    // m_ns: k <= j <= ns_hi
    }

    const int row_base = (b*S + i)*S;
    const unsigned stg_u32 = (unsigned)__cvta_generic_to_shared(stg);
    const unsigned mb_base = (unsigned)__cvta_generic_to_shared(mbars)
                           + (unsigned)(warp * SLOTS * 8);

    // stage one j-row (8 x 512B bulk copies) into slot SL; lane 0 only
    #define STAGE_ROW(ROW, SL) do {                                          \
        if ((ROW) < NE && lane == 0) {                                       \
            const int j_  = lj_e[(ROW)];                                     \
            const int off = (row_base + j_)*S;                               \
            const unsigned sd = stg_u32 + (unsigned)((warp*SLOTS + (SL)) * ROW_BYTES); \
            const unsigned mb = mb_base + (unsigned)((SL) * 8);              \
            asm volatile("mbarrier.arrive.expect_tx.shared::cta.b64 _, [%0], %1;" \
                         :: "r"(mb), "r"((unsigned)ROW_BYTES) : "memory");   \
            bulk512(sd + 0*512, t_be + off, mb);                             \
            bulk512(sd + 1*512, t_eb + off, mb);                             \
            bulk512(sd + 2*512, t_bb + off, mb);                             \
            bulk512(sd + 3*512, t_ee + off, mb);                             \
            bulk512(sd + 4*512, t_cb + off, mb);                             \
            bulk512(sd + 5*512, t_ce + off, mb);                             \
            bulk512(sd + 6*512, t_gb + off, mb);                             \
            bulk512(sd + 7*512, t_ge + off, mb);                             \
        }                                                                    \
    } while (0)

    // ---- phase 1a: warp-local 3-slot ring, q rows via LDG prefetch ----
    STAGE_ROW(warp,           0);
    STAGE_ROW(warp + NWARP,   1);
    STAGE_ROW(warp + 2*NWARP, 2);

    float4 qbTn = {0,0,0,0}, qeTn = {0,0,0,0}, qsn = {0,0,0,0}, qsTn = {0,0,0,0};
    if (warp < NE) {
        const int qof = (b*S + lj_e[warp])*S + k0;
        qbTn = *(const float4*)(g_qbT + qof);
        qeTn = *(const float4*)(g_qeT + qof);
        qsn  = *(const float4*)(g_qs  + qof);
        qsTn = *(const float4*)(g_qsT + qof);
    }

    int slot = 0, par = 0;
    for (int t = warp; t < NE; t += NWARP) {
        const float4 qbTc = qbTn, qeTc = qeTn, qsc = qsn, qsTc = qsTn;
        if (t + NWARP < NE) {                  // prefetch q for next row
            const int qof = (b*S + lj_e[t + NWARP])*S + k0;
            qbTn = *(const float4*)(g_qbT + qof);
            qeTn = *(const float4*)(g_qeT + qof);
            qsn  = *(const float4*)(g_qs  + qof);
            qsTn = *(const float4*)(g_qsT + qof);
        }
        mbar_wait(mb_base + slot*8, (unsigned)par);

        const int j = lj_e[t];
        const float* sb = &stg[(warp*SLOTS + slot) * (SEGS*128) + k0];
        float a_be[4], a_eb[4], a_bb[4], a_ee[4], a_cb[4], a_ce[4], a_gb[4], a_ge[4];
        *(float4*)a_be = *(const float4*)(sb + 0*128);
        *(float4*)a_eb = *(const float4*)(sb + 1*128);
        *(float4*)a_bb = *(const float4*)(sb + 2*128);
        *(float4*)a_ee = *(const float4*)(sb + 3*128);
        *(float4*)a_cb = *(const float4*)(sb + 4*128);
        *(float4*)a_ce = *(const float4*)(sb + 5*128);
        *(float4*)a_gb = *(const float4*)(sb + 6*128);
        *(float4*)a_ge = *(const float4*)(sb + 7*128);
        const float* qbTj = (const float*)&qbTc;
        const float* qeTj = (const float*)&qeTc;
        const float* qsj  = (const float*)&qsc;
        const float* qsTj = (const float*)&qsTc;

        float ab = 0.f, ae1 = 0.f, ae2 = 0.f;
        #pragma unroll
        for (int u = 0; u < 4; ++u) {
            const int k = k0 + u;
            ab  += w_be[u] * a_be[u];
            ab  += w_bb[u] * a_bb[u];
            ab  += (pre_wm[u] * qbTj[u]) * a_cb[u];
            const float wnc = (j >= nc_lo[u] && j <= k) ? pre_wm[u] : 0.f;
            ab  += (wnc * qsj[u]) * a_gb[u];
            ae1 += w_eb[u] * a_eb[u];
            const float wns = (j >= k && j <= ns_hi[u]) ? e4[u] : 0.f;
            ae1 += (wns * qsTj[u]) * a_ge[u];
            ae2 += w_be[u] * a_ee[u];
            ae2 += (pre_wm[u] * qeTj[u]) * a_ce[u];
        }
        // k = j correction for the m_2o (k != j) terms
        #pragma unroll
        for (int u = 0; u < 4; ++u) {
            if (j == k0 + u) {
                ab  -= w_bb[u] * a_bb[u] + (pre_wm[u] * qbTj[u]) * a_cb[u];
                ae2 -= w_be[u] * a_ee[u] + (pre_wm[u] * qeTj[u]) * a_ce[u];
            }
        }
        float ae = ((i != j) ? 1.f : 0.f) * ae1 + ae2;
        #pragma unroll
        for (int o = 16; o; o >>= 1) {
            ab += __shfl_xor_sync(0xffffffffu, ab, o);
            ae += __shfl_xor_sync(0xffffffffu, ae, o);
        }
        if (lane == 0) { sm_ab[j] = ab; sm_ae[j] = ae; }
        __syncwarp();                          // all lanes done reading slot
        STAGE_ROW(t + SLOTS*NWARP, slot);      // refill freed slot
        if (++slot == SLOTS) { slot = 0; par ^= 1; }
    }

    // ---- phase 1b: split term, 4 rows batch-loaded (MLP=4) ----
    for (int jj = warp; jj < NS; jj += NWARP * 4) {
        float v[4][4];
        int jr[4];
        #pragma unroll
        for (int r = 0; r < 4; ++r) {
            const int idx = jj + r * NWARP;
            jr[r] = (idx < NS) ? (int)lj_s[idx] : -1;
            if (jr[r] >= 0)
                *(float4*)v[r] = *(const float4*)(t_sp + (row_base + jr[r])*S + k0);
        }
        #pragma unroll
        for (int r = 0; r < 4; ++r) {
            if (jr[r] < 0) break;                  // warp-uniform
            const int j = jr[r];
            const int mx = (i > j) ? i : j;
            float as_ = 0.f;
            #pragma unroll
            for (int u = 0; u < 4; ++u)
                as_ += ((k0 + u != mx) ? qsk[u] : 0.f) * v[r][u];
            #pragma unroll
            for (int o = 16; o; o >>= 1)
                as_ += __shfl_xor_sync(0xffffffffu, as_, o);
            if (lane == 0) sm_as[j] = as_;
        }
    }

    // ---- phase 2: span_grd_b gather; thread tid owns j = tid ----
    const int j = tid;
    float span = 0.f;
    if (sm_sp[j]) {
        const int mx = (i > j) ? i : j;
        #pragma unroll 8
        for (int t = 0; t < NK; ++t) {
            const int k = lk[t];
            const float w = (!((i <= k) && (j >= k)) && (mx != k)) ? sm_qbT[k] : 0.f;
            span += w * t_gb[((b*S + k)*S + i)*S + j];
        }
    }
    __syncthreads();

    const int o = row_base + tid;
    out[o]         += sm_ab[tid];
    out[BSS + o]   += sm_ae[tid];
    out[2*BSS + o] += sm_as[tid] + span;
}

// ---------------------------------------------------------------------------
// k_spanE: block = (b, j). 512 blocks x 256 threads.
// ---------------------------------------------------------------------------
__global__ void __launch_bounds__(256) k_spanE(
    const float* __restrict__ t_ge,
    float* __restrict__ out)
{
    const int b   = blockIdx.x >> 7;
    const int j   = blockIdx.x & 127;
    const int tid = threadIdx.x;
    const int lane = tid & 31;
    const int warp = tid >> 5;

    if (!g_chart[b*SS + j]) return;

    __shared__ unsigned char sm_chc[S];
    __shared__ float sm_qeT[S];
    __shared__ float sm_acc[256];
    __shared__ short lk[S];
    __shared__ int cK[8];

    bool pK = false;
    if (tid < 128) {
        const unsigned char c0 = g_chart[b*SS + tid];
        pK = (c0 != 0);
        sm_chc[tid] = g_chart[(b*S + ((tid + S - 1) & 127))*S + j];
        sm_qeT[tid] = g_qeT[(b*S + j)*S + tid];
    }
    const unsigned bK = __ballot_sync(0xffffffffu, pK);
    if (lane == 0) cK[warp] = __popc(bK);
    __syncthreads();
    int oK = 0;
    #pragma unroll
    for (int w = 0; w < 8; ++w) if (w < warp) oK += cK[w];
    if (pK) lk[oK + __popc(bK & ((1u << lane) - 1u))] = (short)tid;
    __syncthreads();
    const int NK = cK[0] + cK[1] + cK[2] + cK[3];

    const int i  = tid & 127;
    const int kh = tid >> 7;
    float acc = 0.f;
    if (sm_chc[i]) {
        const int mx = (i > j) ? i : j;
        #pragma unroll 8
        for (int t = kh; t < NK; t += 2) {
            const int k = lk[t];
            const float w = (!((i <= k) && (j >= k)) && (mx != k)) ? sm_qeT[k] : 0.f;
            acc += w * t_ge[((b*S + k)*S + j)*S + i];
        }
    }
    sm_acc[tid] = acc;
    __syncthreads();
    if (tid < 128)
        out[2*BSS + (b*S + tid)*S + j] += sm_acc[tid] + sm_acc[tid + 128];
}

// ---------------------------------------------------------------------------
extern "C" void kernel_launch(void* const* d_in, const int* in_sizes, int n_in,
                              void* d_out, int out_size)
{
    const float* s_const     = (const float*)d_in[0];
    const float* s_arg_begin = (const float*)d_in[1];
    const float* s_arg_end   = (const float*)d_in[2];
    const float* s_sib_be    = (const float*)d_in[3];
    const float* s_sib_eb    = (const float*)d_in[4];
    const float* s_sib_bb    = (const float*)d_in[5];
    const float* s_sib_ee    = (const float*)d_in[6];
    const float* s_cop_b     = (const float*)d_in[7];
    const float* s_cop_e     = (const float*)d_in[8];
    const float* s_grd_b     = (const float*)d_in[9];
    const float* s_grd_e     = (const float*)d_in[10];
    const float* s_split     = (const float*)d_in[11];
    const void*  edge        = d_in[12];
    const void*  chartm      = d_in[13];
    float* out = (float*)d_out;

    // host-side, idempotent, capture-safe
    cudaFuncSetAttribute(k_main, cudaFuncAttributeMaxDynamicSharedMemorySize,
                         SMEM_DYN);

    k_detect<<<1, 128>>>((const unsigned int*)edge, (const unsigned int*)chartm);
    k_prep<<<BSS/4/128, 128>>>(edge, chartm, (const float4*)s_arg_begin,
                               (const float4*)s_arg_end, (const float4*)s_const,
                               (float4*)out);

    for (int it = 0; it < 3; ++it) {
        k_sigmoid<<<BSS/128, 128>>>(out);
        // k_main at launch index 3 on first iter -> ncu capture slot
        k_main<<<B * S, 128, SMEM_DYN>>>(s_sib_be, s_sib_eb, s_sib_bb, s_sib_ee,
                                         s_cop_b, s_cop_e, s_grd_b, s_grd_e,
                                         s_split, out);
        k_spanE<<<B * S, 256>>>(s_grd_e, out);
    }
}